// round 2
// baseline (speedup 1.0000x reference)
#include <cuda_runtime.h>
#include <math.h>

#define Qn 1024
#define Tn 256
#define Nn 100
#define Kn 300      // 3*N flattened reduction dim
#define PITCH 306   // pred tile pitch: even (8B align) and 306%32=18 -> bank-split q-lanes

typedef unsigned long long u64;

__device__ float g_cls[Qn * 8];   // [0..3]=log(type_prob+eps), [4]=log(valid0+eps), [5..6]=log(closed+eps), [7]=p2
__device__ float g_v2[Tn];
__device__ int   g_lab[Tn];
__device__ int   g_clo[Tn];

// packed fp32x2 FMA: c = a*b + c  (elementwise on the two fp32 halves) -> SASS FFMA2
__device__ __forceinline__ void ffma2(u64& c, u64 a, u64 b) {
    asm("fma.rn.f32x2 %0, %1, %2, %3;" : "=l"(c) : "l"(a), "l"(b), "l"(c));
}
__device__ __forceinline__ float pairsum(u64 v) {
    return __uint_as_float((unsigned)v) + __uint_as_float((unsigned)(v >> 32));
}

// ---------------------------------------------------------------------------
// Precompute: per-q softmax logs + p2, per-t v2, int64/int32 label decode.
// ---------------------------------------------------------------------------
__global__ void pre_kernel(const float* __restrict__ pred,
                           const float* __restrict__ vlog,
                           const float* __restrict__ tlog,
                           const float* __restrict__ clog,
                           const float* __restrict__ tgt,
                           const int* __restrict__ lab32,
                           const int* __restrict__ clo32)
{
    const int tid = threadIdx.x;
    if (blockIdx.x < 4) {
        const int q = blockIdx.x * 256 + tid;
        float x0 = tlog[q*4+0], x1 = tlog[q*4+1], x2 = tlog[q*4+2], x3 = tlog[q*4+3];
        float m  = fmaxf(fmaxf(x0, x1), fmaxf(x2, x3));
        float e0 = expf(x0-m), e1 = expf(x1-m), e2 = expf(x2-m), e3 = expf(x3-m);
        float s  = e0 + e1 + e2 + e3;
        g_cls[q*8+0] = logf(e0/s + 1e-6f);
        g_cls[q*8+1] = logf(e1/s + 1e-6f);
        g_cls[q*8+2] = logf(e2/s + 1e-6f);
        g_cls[q*8+3] = logf(e3/s + 1e-6f);
        float a0 = vlog[q*2+0], a1 = vlog[q*2+1];
        float ma = fmaxf(a0, a1);
        float f0 = expf(a0-ma), f1 = expf(a1-ma);
        g_cls[q*8+4] = logf(f0/(f0+f1) + 1e-6f);
        float b0 = clog[q*2+0], b1 = clog[q*2+1];
        float mb = fmaxf(b0, b1);
        float h0 = expf(b0-mb), h1 = expf(b1-mb);
        float hs = h0 + h1;
        g_cls[q*8+5] = logf(h0/hs + 1e-6f);
        g_cls[q*8+6] = logf(h1/hs + 1e-6f);
        float p2 = 0.f;
        for (int k = 0; k < Kn; k++) { float v = pred[q*Kn+k]; p2 = fmaf(v, v, p2); }
        g_cls[q*8+7] = p2;
    } else {
        // dtype detection: int64 data read as int32 has all odd words == 0
        __shared__ int flag;
        if (tid == 0) flag = 0;
        __syncthreads();
        if (tid < 128) {
            if (lab32[2*tid+1] != 0 || clo32[2*tid+1] != 0) atomicOr(&flag, 1);
        }
        __syncthreads();
        const int t = tid;  // 256 threads == Tn
        int lv, cv;
        if (flag) { lv = lab32[t]; cv = clo32[t]; }
        else {
            lv = (int)((const long long*)lab32)[t];
            cv = (int)((const long long*)clo32)[t];
        }
        g_lab[t] = lv;
        g_clo[t] = cv;
        float v2 = 0.f;
        for (int k = 0; k < Kn; k++) { float v = tgt[t*Kn+k]; v2 = fmaf(v, v, v2); }
        g_v2[t] = v2;
    }
}

// extended (circular) target value: idx in [0, 600)
__device__ __forceinline__ float sext_fwd(const float* __restrict__ tg, int idx) {
    int m = idx / 3, c = idx - m * 3;
    int mm = (m >= Nn) ? (m - Nn) : m;
    return tg[mm * 3 + c];
}
__device__ __forceinline__ float sext_bwd(const float* __restrict__ tg, int idx) {
    int m = idx / 3, c = idx - m * 3;
    int mm = (m >= Nn) ? (m - Nn) : m;
    return tg[(Nn - 1 - mm) * 3 + c];
}

// ---------------------------------------------------------------------------
__device__ __forceinline__ void epilogue_write(
    float best_ab, int ids, int t, int q, int clos,
    const float* __restrict__ clw, float* __restrict__ out, int write_ids)
{
    const float p2 = g_cls[q*8+7];
    float d2 = fmaxf(g_v2[t] + p2 - 2.0f * best_ab, 0.0f) / 100.0f;
    const int lab = g_lab[t];
    float cls = g_cls[q*8+lab] + g_cls[q*8+4] + g_cls[q*8+5+clos];
    float C = d2 * clw[t] - cls;
    out[q * Tn + t] = C;
    if (write_ids) out[Qn * Tn + q * Tn + t] = (float)ids;
}

__global__ void __launch_bounds__(256, 2)
match_kernel(const float* __restrict__ pred, const float* __restrict__ tgt,
             const float* __restrict__ clw, float* __restrict__ out, int write_ids)
{
    extern __shared__ float sm[];
    float* predsh = sm;                      // 64 * PITCH floats
    float* spf    = sm + 64 * PITCH;         // 600 float2 = 1200 floats: (sext[j], sext[j+1]) fwd
    float* spb    = spf + 1200;              // 1200 floats: bwd pairs
    float* redv   = spb + 1200;              // 128
    int*   redi   = (int*)(redv + 128);      // 128

    const int t   = blockIdx.x;
    const int q0  = blockIdx.y * 64;
    const int tid = threadIdx.x;
    const float* tg = tgt + t * Kn;

    // stage pred tile: coalesced global read, conflict-free shared write
    for (int idx = tid; idx < 64 * Kn; idx += 256) {
        int q = idx / Kn;
        int k = idx - q * Kn;
        predsh[q * PITCH + k] = pred[q0 * Kn + idx];
    }
    // build pair arrays: spf[j] = (sext_f[j], sext_f[j+1]); max index read is 598 (.y -> 599)
    for (int j = tid; j < 600; j += 256) {
        float f0 = sext_fwd(tg, j);
        float f1 = (j < 599) ? sext_fwd(tg, j + 1) : 0.f;
        float b0 = sext_bwd(tg, j);
        float b1 = (j < 599) ? sext_bwd(tg, j + 1) : 0.f;
        *(float2*)(spf + 2 * j) = make_float2(f0, f1);
        *(float2*)(spb + 2 * j) = make_float2(b0, b1);
    }
    const int clos = g_clo[t];
    __syncthreads();

    if (clos) {
        // ---- heavy path: all 200 variants, packed f32x2 FMA along k ----
        const int lane  = tid & 31;
        const int w     = tid >> 5;
        const int vlane = lane & 15;
        const int qlane = lane >> 4;
        const int wq    = w & 3;
        const int dir   = w >> 2;      // 0 = fwd variants, 1 = bwd variants
        const u64* spu  = (const u64*)(dir ? spb : spf);   // pair array as u64
        const int qb = wq * 16 + qlane * 8;
        const float* pb = predsh + qb * PITCH;

        u64 acc[7][8];
        #pragma unroll
        for (int i = 0; i < 7; i++)
            #pragma unroll
            for (int u = 0; u < 8; u++) acc[i][u] = 0ull;

        int off[7];
        #pragma unroll
        for (int i = 0; i < 7; i++) {
            int v = vlane + 16 * i;
            if (v > 99) v = 99;            // clamped duplicates: harmless for max
            off[i] = (100 - v) * 3;
        }

        #pragma unroll 2
        for (int k = 0; k < Kn; k += 2) {
            u64 p[8];
            #pragma unroll
            for (int u = 0; u < 8; u++)
                p[u] = *(const u64*)(pb + u * PITCH + k);   // 8B-aligned: PITCH,k even
            #pragma unroll
            for (int i = 0; i < 7; i++) {
                u64 s = spu[k + off[i]];                     // (sext[k+off], sext[k+off+1])
                #pragma unroll
                for (int u = 0; u < 8; u++)
                    ffma2(acc[i][u], p[u], s);
            }
        }

        // per-q max(ab) with first-index tie-break, reduce across 16 v-lanes
        #pragma unroll
        for (int u = 0; u < 8; u++) {
            float bv = pairsum(acc[0][u]);
            int   bx = (vlane > 99) ? 99 : vlane;
            #pragma unroll
            for (int i = 1; i < 7; i++) {
                int v = vlane + 16 * i;
                if (v > 99) v = 99;
                float av = pairsum(acc[i][u]);
                if (av > bv) { bv = av; bx = v; }   // strict >: keeps smaller v on tie
            }
            #pragma unroll
            for (int m = 8; m >= 1; m >>= 1) {
                float ov = __shfl_xor_sync(0xffffffffu, bv, m);
                int   ox = __shfl_xor_sync(0xffffffffu, bx, m);
                if (ov > bv || (ov == bv && ox < bx)) { bv = ov; bx = ox; }
            }
            if (vlane == 0) {
                redv[dir * 64 + qb + u] = bv;
                redi[dir * 64 + qb + u] = bx;
            }
        }
        __syncthreads();

        if (tid < 64) {
            float bf = redv[tid];      int xf = redi[tid];
            float bw = redv[64 + tid]; int xb = redi[64 + tid];
            float best; int ids;
            if (bw > bf) { best = bw; ids = 99 - xb; }  // bwd raw idx = 100+xb -> 2n-1-idx
            else         { best = bf; ids = xf; }       // tie -> fwd (smaller raw index)
            epilogue_write(best, ids, t, q0 + tid, clos, clw, out, write_ids);
        }
    } else {
        // ---- light path: open curve needs only variants v=0 (fwd) and v=n (bwd) ----
        if (tid < 64) {
            const float* pq = predsh + tid * PITCH;
            u64 af = 0ull, ab = 0ull;
            const u64* suf = (const u64*)spf;
            const u64* sub = (const u64*)spb;
            #pragma unroll 2
            for (int k = 0; k < Kn; k += 2) {
                u64 p = *(const u64*)(pq + k);
                ffma2(af, p, suf[k + 300]);
                ffma2(ab, p, sub[k + 300]);
            }
            float best = fmaxf(pairsum(af), pairsum(ab));
            epilogue_write(best, 0, t, q0 + tid, clos, clw, out, write_ids);
        }
    }
}

// ---------------------------------------------------------------------------
extern "C" void kernel_launch(void* const* d_in, const int* in_sizes, int n_in,
                              void* d_out, int out_size)
{
    const float* pred = (const float*)d_in[0];   // pred_curve_points (1,Q,N,3)
    const float* vlog = (const float*)d_in[1];   // pred_curve_logits (1,Q,2)
    const float* tlog = (const float*)d_in[2];   // pred_curve_type   (1,Q,4)
    const float* clog = (const float*)d_in[3];   // closed_curve_logits (1,Q,2)
    const float* tgt  = (const float*)d_in[4];   // tgt_curve_points (T,N,3)
    const int*   lab  = (const int*)d_in[5];     // tgt_labels (int32 or int64)
    const int*   clo  = (const int*)d_in[6];     // tgt_is_closed
    const float* clw  = (const float*)d_in[7];   // curve_length_weighting (T)
    float* out = (float*)d_out;

    const int smem = (64 * PITCH + 1200 * 2 + 128) * (int)sizeof(float) + 128 * (int)sizeof(int);
    cudaFuncSetAttribute(match_kernel, cudaFuncAttributeMaxDynamicSharedMemorySize, smem);

    const int write_ids = (out_size >= 2 * Qn * Tn) ? 1 : 0;

    pre_kernel<<<5, 256>>>(pred, vlog, tlog, clog, tgt, lab, clo);
    match_kernel<<<dim3(Tn, 16), 256, smem>>>(pred, tgt, clw, out, write_ids);
}

// round 3
// speedup vs baseline: 2.2235x; 2.2235x over previous
#include <cuda_runtime.h>
#include <math.h>

#define Qn 1024
#define Tn 256
#define Nn 100
#define Kn 300      // 3*N flattened reduction dim
#define PITCH 306   // pred tile pitch: even (8B align) and 306%32=18 -> bank-split q-lanes
#define QT 32       // q tile per block

typedef unsigned long long u64;

__device__ float g_cls[Qn * 8];   // [0..3]=log(type_prob+eps), [4]=log(valid0+eps), [5..6]=log(closed+eps), [7]=p2
__device__ float g_v2[Tn];
__device__ int   g_lab[Tn];
__device__ int   g_clo[Tn];

// packed fp32x2 FMA: c = a*b + c  -> SASS FFMA2
__device__ __forceinline__ void ffma2(u64& c, u64 a, u64 b) {
    asm("fma.rn.f32x2 %0, %1, %2, %3;" : "=l"(c) : "l"(a), "l"(b), "l"(c));
}
__device__ __forceinline__ float pairsum(u64 v) {
    return __uint_as_float((unsigned)v) + __uint_as_float((unsigned)(v >> 32));
}

// ---------------------------------------------------------------------------
__global__ void pre_kernel(const float* __restrict__ pred,
                           const float* __restrict__ vlog,
                           const float* __restrict__ tlog,
                           const float* __restrict__ clog,
                           const float* __restrict__ tgt,
                           const int* __restrict__ lab32,
                           const int* __restrict__ clo32)
{
    const int tid = threadIdx.x;
    if (blockIdx.x < 4) {
        const int q = blockIdx.x * 256 + tid;
        float x0 = tlog[q*4+0], x1 = tlog[q*4+1], x2 = tlog[q*4+2], x3 = tlog[q*4+3];
        float m  = fmaxf(fmaxf(x0, x1), fmaxf(x2, x3));
        float e0 = expf(x0-m), e1 = expf(x1-m), e2 = expf(x2-m), e3 = expf(x3-m);
        float s  = e0 + e1 + e2 + e3;
        g_cls[q*8+0] = logf(e0/s + 1e-6f);
        g_cls[q*8+1] = logf(e1/s + 1e-6f);
        g_cls[q*8+2] = logf(e2/s + 1e-6f);
        g_cls[q*8+3] = logf(e3/s + 1e-6f);
        float a0 = vlog[q*2+0], a1 = vlog[q*2+1];
        float ma = fmaxf(a0, a1);
        float f0 = expf(a0-ma), f1 = expf(a1-ma);
        g_cls[q*8+4] = logf(f0/(f0+f1) + 1e-6f);
        float b0 = clog[q*2+0], b1 = clog[q*2+1];
        float mb = fmaxf(b0, b1);
        float h0 = expf(b0-mb), h1 = expf(b1-mb);
        float hs = h0 + h1;
        g_cls[q*8+5] = logf(h0/hs + 1e-6f);
        g_cls[q*8+6] = logf(h1/hs + 1e-6f);
        float p2 = 0.f;
        for (int k = 0; k < Kn; k++) { float v = pred[q*Kn+k]; p2 = fmaf(v, v, p2); }
        g_cls[q*8+7] = p2;
    } else {
        // dtype detection: int64 data read as int32 has all odd words == 0
        __shared__ int flag;
        if (tid == 0) flag = 0;
        __syncthreads();
        if (tid < 128) {
            if (lab32[2*tid+1] != 0 || clo32[2*tid+1] != 0) atomicOr(&flag, 1);
        }
        __syncthreads();
        const int t = tid;
        int lv, cv;
        if (flag) { lv = lab32[t]; cv = clo32[t]; }
        else {
            lv = (int)((const long long*)lab32)[t];
            cv = (int)((const long long*)clo32)[t];
        }
        g_lab[t] = lv;
        g_clo[t] = cv;
        float v2 = 0.f;
        for (int k = 0; k < Kn; k++) { float v = tgt[t*Kn+k]; v2 = fmaf(v, v, v2); }
        g_v2[t] = v2;
    }
}

// extended (circular) target value: idx in [0, 600)
__device__ __forceinline__ float sext_fwd(const float* __restrict__ tg, int idx) {
    int m = idx / 3, c = idx - m * 3;
    int mm = (m >= Nn) ? (m - Nn) : m;
    return tg[mm * 3 + c];
}
__device__ __forceinline__ float sext_bwd(const float* __restrict__ tg, int idx) {
    int m = idx / 3, c = idx - m * 3;
    int mm = (m >= Nn) ? (m - Nn) : m;
    return tg[(Nn - 1 - mm) * 3 + c];
}

// ---------------------------------------------------------------------------
__device__ __forceinline__ void epilogue_write(
    float best_ab, int ids, int t, int q, int clos,
    const float* __restrict__ clw, float* __restrict__ out, int write_ids)
{
    const float p2 = g_cls[q*8+7];
    float d2 = fmaxf(g_v2[t] + p2 - 2.0f * best_ab, 0.0f) / 100.0f;
    const int lab = g_lab[t];
    float cls = g_cls[q*8+lab] + g_cls[q*8+4] + g_cls[q*8+5+clos];
    float C = d2 * clw[t] - cls;
    out[q * Tn + t] = C;
    if (write_ids) out[Qn * Tn + q * Tn + t] = (float)ids;
}

__global__ void __launch_bounds__(128, 3)
match_kernel(const float* __restrict__ pred, const float* __restrict__ tgt,
             const float* __restrict__ clw, float* __restrict__ out, int write_ids)
{
    extern __shared__ float sm[];
    float* predsh = sm;                      // QT * PITCH floats
    float* spf    = sm + QT * PITCH;         // 600 float2 = 1200 floats
    float* spb    = spf + 1200;              // 1200 floats
    float* redv   = spb + 1200;              // 64
    int*   redi   = (int*)(redv + 64);       // 64

    const int t   = blockIdx.x;
    const int q0  = blockIdx.y * QT;
    const int tid = threadIdx.x;
    const float* tg = tgt + t * Kn;
    const int clos = g_clo[t];

    if (clos) {
        // stage pred tile: coalesced global read, conflict-free shared write
        for (int idx = tid; idx < QT * Kn; idx += 128) {
            int q = idx / Kn;
            int k = idx - q * Kn;
            predsh[q * PITCH + k] = pred[q0 * Kn + idx];
        }
    }
    // build pair arrays: spf[j] = (sext_f[j], sext_f[j+1])
    for (int j = tid; j < 600; j += 128) {
        float f0 = sext_fwd(tg, j);
        float f1 = (j < 599) ? sext_fwd(tg, j + 1) : 0.f;
        float b0 = sext_bwd(tg, j);
        float b1 = (j < 599) ? sext_bwd(tg, j + 1) : 0.f;
        *(float2*)(spf + 2 * j) = make_float2(f0, f1);
        *(float2*)(spb + 2 * j) = make_float2(b0, b1);
    }
    __syncthreads();

    if (clos) {
        // ---- heavy path: 4 warps = dir(2) x wq(2), packed f32x2 FMA along k ----
        const int lane  = tid & 31;
        const int w     = tid >> 5;
        const int vlane = lane & 15;   // s pair loads: 6-bank stride, conflict-free
        const int qlane = lane >> 4;
        const int wq    = w & 1;
        const int dir   = w >> 1;      // 0 = fwd, 1 = bwd
        const u64* spu  = (const u64*)(dir ? spb : spf);
        const int qb = wq * 16 + qlane * 8;
        const float* pb = predsh + qb * PITCH;

        u64 acc[7][8];
        #pragma unroll
        for (int i = 0; i < 7; i++)
            #pragma unroll
            for (int u = 0; u < 8; u++) acc[i][u] = 0ull;

        int off[7];
        #pragma unroll
        for (int i = 0; i < 7; i++) {
            int v = vlane + 16 * i;
            if (v > 99) v = 99;            // clamped duplicates: harmless for max
            off[i] = (100 - v) * 3;
        }

        #pragma unroll 1
        for (int k = 0; k < Kn; k += 2) {
            u64 p[8];
            #pragma unroll
            for (int u = 0; u < 8; u++)
                p[u] = *(const u64*)(pb + u * PITCH + k);
            #pragma unroll
            for (int i = 0; i < 7; i++) {
                u64 s = spu[k + off[i]];
                #pragma unroll
                for (int u = 0; u < 8; u++)
                    ffma2(acc[i][u], p[u], s);
            }
        }

        // per-q max(ab) with first-index tie-break, reduce across 16 v-lanes
        #pragma unroll
        for (int u = 0; u < 8; u++) {
            float bv = pairsum(acc[0][u]);
            int   bx = (vlane > 99) ? 99 : vlane;
            #pragma unroll
            for (int i = 1; i < 7; i++) {
                int v = vlane + 16 * i;
                if (v > 99) v = 99;
                float av = pairsum(acc[i][u]);
                if (av > bv) { bv = av; bx = v; }   // strict >: keeps smaller v on tie
            }
            #pragma unroll
            for (int m = 8; m >= 1; m >>= 1) {
                float ov = __shfl_xor_sync(0xffffffffu, bv, m);
                int   ox = __shfl_xor_sync(0xffffffffu, bx, m);
                if (ov > bv || (ov == bv && ox < bx)) { bv = ov; bx = ox; }
            }
            if (vlane == 0) {
                redv[dir * 32 + qb + u] = bv;
                redi[dir * 32 + qb + u] = bx;
            }
        }
        __syncthreads();

        if (tid < QT) {
            float bf = redv[tid];      int xf = redi[tid];
            float bw = redv[32 + tid]; int xb = redi[32 + tid];
            float best; int ids;
            if (bw > bf) { best = bw; ids = 99 - xb; }  // bwd raw idx = 100+xb -> 2n-1-idx
            else         { best = bf; ids = xf; }       // tie -> fwd (smaller raw index)
            epilogue_write(best, ids, t, q0 + tid, clos, clw, out, write_ids);
        }
    } else {
        // ---- light path: open curve, variants v=0 (fwd) and v=n (bwd) only ----
        // read pred straight from global (L2-resident), skip tile staging
        if (tid < QT) {
            const u64* pq  = (const u64*)(pred + (q0 + tid) * Kn);
            const u64* suf = (const u64*)spf;
            const u64* sub = (const u64*)spb;
            u64 af = 0ull, ab = 0ull;
            #pragma unroll 2
            for (int k2 = 0; k2 < Kn / 2; k2++) {
                u64 p = pq[k2];
                ffma2(af, p, suf[2 * k2 + 300]);
                ffma2(ab, p, sub[2 * k2 + 300]);
            }
            float best = fmaxf(pairsum(af), pairsum(ab));
            epilogue_write(best, 0, t, q0 + tid, clos, clw, out, write_ids);
        }
    }
}

// ---------------------------------------------------------------------------
extern "C" void kernel_launch(void* const* d_in, const int* in_sizes, int n_in,
                              void* d_out, int out_size)
{
    const float* pred = (const float*)d_in[0];   // pred_curve_points (1,Q,N,3)
    const float* vlog = (const float*)d_in[1];   // pred_curve_logits (1,Q,2)
    const float* tlog = (const float*)d_in[2];   // pred_curve_type   (1,Q,4)
    const float* clog = (const float*)d_in[3];   // closed_curve_logits (1,Q,2)
    const float* tgt  = (const float*)d_in[4];   // tgt_curve_points (T,N,3)
    const int*   lab  = (const int*)d_in[5];     // tgt_labels (int32 or int64)
    const int*   clo  = (const int*)d_in[6];     // tgt_is_closed
    const float* clw  = (const float*)d_in[7];   // curve_length_weighting (T)
    float* out = (float*)d_out;

    const int smem = (QT * PITCH + 2400 + 64) * (int)sizeof(float) + 64 * (int)sizeof(int);
    cudaFuncSetAttribute(match_kernel, cudaFuncAttributeMaxDynamicSharedMemorySize, smem);

    const int write_ids = (out_size >= 2 * Qn * Tn) ? 1 : 0;

    pre_kernel<<<5, 256>>>(pred, vlog, tlog, clog, tgt, lab, clo);
    match_kernel<<<dim3(Tn, Qn / QT), 128, smem>>>(pred, tgt, clw, out, write_ids);
}